// round 7
// baseline (speedup 1.0000x reference)
#include <cuda_runtime.h>
#include <cuda_bf16.h>
#include <cstdint>

#define N_NODES 20000
#define R_REL   8
#define KA      2048
#define KTOT    2304
#define BK      32
#define LDT     40
#define NSEG_MX (N_NODES * R_REL)
#define E_MAX   650000

// ---------------- static device scratch ----------------
__device__ __nv_bfloat16 g_Ah[(size_t)N_NODES * KA];
__device__ __nv_bfloat16 g_Al[(size_t)N_NODES * KA];
__device__ __nv_bfloat16 g_X1h[(size_t)N_NODES * 256];
__device__ __nv_bfloat16 g_X1l[(size_t)N_NODES * 256];
__device__ __nv_bfloat16 g_X2h[(size_t)N_NODES * 256];
__device__ __nv_bfloat16 g_X2l[(size_t)N_NODES * 256];
__device__ float g_h[(size_t)N_NODES * 256];
__device__ int   g_cnt[NSEG_MX];
__device__ int   g_off[NSEG_MX + 1];
__device__ int   g_cur[NSEG_MX];
__device__ int   g_part[(NSEG_MX + 255) / 256];
__device__ int   g_sorted[E_MAX];
__device__ int   g_is64;
__device__ __nv_bfloat16 g_Wh1[256 * KTOT];
__device__ __nv_bfloat16 g_Wl1[256 * KTOT];
__device__ __nv_bfloat16 g_Wh2[128 * KTOT];
__device__ __nv_bfloat16 g_Wl2[128 * KTOT];

__device__ __forceinline__ int load_idx(const void* p, long long i, int is64) {
    return is64 ? (int)((const long long*)p)[i] : ((const int*)p)[i];
}

// ---------------- prep kernels ----------------
__global__ void k_detect_zero(const unsigned* __restrict__ ei_words, int nwords, int nseg) {
    int i = blockIdx.x * blockDim.x + threadIdx.x;
    if (i == 0) {
        int is64 = 1;
        int lim = nwords < 256 ? nwords : 256;
        for (int j = 1; j < lim; j += 2)
            if (ei_words[j] != 0u) { is64 = 0; break; }
        g_is64 = is64;
    }
    if (i < nseg) g_cnt[i] = 0;
}

__global__ void k_count(const void* __restrict__ ei, const void* __restrict__ et, int E) {
    int e = blockIdx.x * blockDim.x + threadIdx.x;
    if (e >= E) return;
    int is64 = g_is64;
    int dst = load_idx(ei, (long long)E + e, is64);
    int r   = load_idx(et, e, is64);
    atomicAdd(&g_cnt[dst * R_REL + r], 1);
}

__global__ void k_scan1(int nseg) {
    __shared__ int sh[256];
    int b = blockIdx.x, t = threadIdx.x, i = b * 256 + t;
    int v = (i < nseg) ? g_cnt[i] : 0;
    sh[t] = v; __syncthreads();
#pragma unroll
    for (int d = 1; d < 256; d <<= 1) {
        int add = (t >= d) ? sh[t - d] : 0;
        __syncthreads();
        sh[t] += add;
        __syncthreads();
    }
    if (i < nseg) g_off[i + 1] = sh[t];
    if (t == 255) g_part[b] = sh[255];
}

__global__ void k_scan2(int nseg) {
    __shared__ int sh[256];
    int b = blockIdx.x, t = threadIdx.x, i = b * 256 + t;
    int s = 0;
    for (int j = t; j < b; j += 256) s += g_part[j];
    sh[t] = s; __syncthreads();
#pragma unroll
    for (int d = 128; d > 0; d >>= 1) { if (t < d) sh[t] += sh[t + d]; __syncthreads(); }
    int base = sh[0];
    int selfv = (i < nseg) ? g_off[i + 1] : 0;
    int prev  = (t > 0 && i < nseg) ? g_off[i] : 0;
    __syncthreads();
    if (i < nseg) {
        g_off[i + 1] = selfv + base;
        g_cur[i] = base + prev;
    }
    if (b == 0 && t == 0) g_off[0] = 0;
}

__global__ void k_scatter(const void* __restrict__ ei, const void* __restrict__ et, int E) {
    int e = blockIdx.x * blockDim.x + threadIdx.x;
    if (e >= E) return;
    int is64 = g_is64;
    int src = load_idx(ei, e, is64);
    int dst = load_idx(ei, (long long)E + e, is64);
    int r   = load_idx(et, e, is64);
    int pos = atomicAdd(&g_cur[dst * R_REL + r], 1);
    g_sorted[pos] = src;
}

// ---------------- CSR aggregation: warp per (dst,rel) segment ----------------
__global__ __launch_bounds__(256) void k_agg_csr(
    const float* __restrict__ x,
    __nv_bfloat16* __restrict__ Ah, __nv_bfloat16* __restrict__ Al, int nseg)
{
    int w = (int)(((size_t)blockIdx.x * blockDim.x + threadIdx.x) >> 5);
    if (w >= nseg) return;
    int lane = threadIdx.x & 31;
    int beg = g_off[w], end = g_off[w + 1];
    int cnt = end - beg;

    float4 a0 = make_float4(0.f, 0.f, 0.f, 0.f);
    float4 a1 = make_float4(0.f, 0.f, 0.f, 0.f);

    for (int base = beg; base < end; base += 32) {
        int m = end - base; if (m > 32) m = 32;
        int myE = (lane < m) ? g_sorted[base + lane] : 0;
        for (int j = 0; j < m; ++j) {
            int src = __shfl_sync(0xffffffffu, myE, j);
            const float4* xs = (const float4*)(x + (size_t)src * 256 + lane * 8);
            float4 v0 = xs[0], v1 = xs[1];
            a0.x += v0.x; a0.y += v0.y; a0.z += v0.z; a0.w += v0.w;
            a1.x += v1.x; a1.y += v1.y; a1.z += v1.z; a1.w += v1.w;
        }
    }
    float s = cnt > 0 ? 1.0f / (float)cnt : 0.0f;
    a0.x *= s; a0.y *= s; a0.z *= s; a0.w *= s;
    a1.x *= s; a1.y *= s; a1.z *= s; a1.w *= s;

    __nv_bfloat162 h01 = __floats2bfloat162_rn(a0.x, a0.y);
    __nv_bfloat162 h23 = __floats2bfloat162_rn(a0.z, a0.w);
    __nv_bfloat162 h45 = __floats2bfloat162_rn(a1.x, a1.y);
    __nv_bfloat162 h67 = __floats2bfloat162_rn(a1.z, a1.w);
    __nv_bfloat162 l01 = __floats2bfloat162_rn(a0.x - __low2float(h01), a0.y - __high2float(h01));
    __nv_bfloat162 l23 = __floats2bfloat162_rn(a0.z - __low2float(h23), a0.w - __high2float(h23));
    __nv_bfloat162 l45 = __floats2bfloat162_rn(a1.x - __low2float(h45), a1.y - __high2float(h45));
    __nv_bfloat162 l67 = __floats2bfloat162_rn(a1.z - __low2float(h67), a1.w - __high2float(h67));

    size_t o = (size_t)w * 256 + lane * 8;
    uint4 hv, lv;
    hv.x = *(unsigned*)&h01; hv.y = *(unsigned*)&h23; hv.z = *(unsigned*)&h45; hv.w = *(unsigned*)&h67;
    lv.x = *(unsigned*)&l01; lv.y = *(unsigned*)&l23; lv.z = *(unsigned*)&l45; lv.w = *(unsigned*)&l67;
    *(uint4*)(Ah + o) = hv;
    *(uint4*)(Al + o) = lv;
}

// ---------------- weight / input conversion ----------------
__global__ void k_wconv(const float* __restrict__ W1, const float* __restrict__ r1,
                        const float* __restrict__ W2, const float* __restrict__ r2) {
    int idx = blockIdx.x * blockDim.x + threadIdx.x;
    const int L1 = 256 * KTOT, L2 = 128 * KTOT;
    if (idx < L1) {
        int nrow = idx / KTOT, k = idx % KTOT;
        float v = (k < KA) ? W1[(size_t)k * 256 + nrow] : r1[(size_t)(k - KA) * 256 + nrow];
        __nv_bfloat16 h = __float2bfloat16_rn(v);
        g_Wh1[idx] = h;
        g_Wl1[idx] = __float2bfloat16_rn(v - __bfloat162float(h));
    } else if (idx < L1 + L2) {
        int i2 = idx - L1;
        int nrow = i2 / KTOT, k = i2 % KTOT;
        float v = (k < KA) ? W2[(size_t)k * 128 + nrow] : r2[(size_t)(k - KA) * 128 + nrow];
        __nv_bfloat16 h = __float2bfloat16_rn(v);
        g_Wh2[i2] = h;
        g_Wl2[i2] = __float2bfloat16_rn(v - __bfloat162float(h));
    }
}

__global__ void k_xconv(const float* __restrict__ x, int total) {
    int idx = blockIdx.x * blockDim.x + threadIdx.x;
    if (idx >= total) return;
    float v = x[idx];
    __nv_bfloat16 h = __float2bfloat16_rn(v);
    g_X1h[idx] = h;
    g_X1l[idx] = __float2bfloat16_rn(v - __bfloat162float(h));
}

// ---------------- pipelined mma.sync bf16-split GEMM (ldmatrix frags) --------
#define MMA_BF16(C, A0, A1, A2, A3, B0, B1)                                   \
    asm volatile(                                                             \
        "mma.sync.aligned.m16n8k16.row.col.f32.bf16.bf16.f32 "                \
        "{%0,%1,%2,%3}, {%4,%5,%6,%7}, {%8,%9}, {%0,%1,%2,%3};"               \
        : "+f"(C[0]), "+f"(C[1]), "+f"(C[2]), "+f"(C[3])                      \
        : "r"(A0), "r"(A1), "r"(A2), "r"(A3), "r"(B0), "r"(B1))

#define LDSM4(R, ADDR)                                                        \
    asm volatile("ldmatrix.sync.aligned.m8n8.x4.shared.b16 "                  \
                 "{%0,%1,%2,%3}, [%4];"                                       \
                 : "=r"((R)[0]), "=r"((R)[1]), "=r"((R)[2]), "=r"((R)[3])     \
                 : "r"(ADDR))

__device__ __forceinline__ uint32_t smem_u32(const void* p) {
    uint32_t a;
    asm("{ .reg .u64 t; cvta.to.shared.u64 t, %1; cvt.u32.u64 %0, t; }" : "=r"(a) : "l"(p));
    return a;
}
__device__ __forceinline__ void cpa16(uint32_t dst, const void* src) {
    asm volatile("cp.async.cg.shared.global [%0], [%1], 16;" :: "r"(dst), "l"(src));
}

#define PLANE_BYTES (128 * LDT * 2)            // 10240
#define OFF_AH 0
#define OFF_AL (PLANE_BYTES)
#define OFF_BH (2 * PLANE_BYTES)
#define OFF_BL (3 * PLANE_BYTES)
#define STAGE_BYTES (4 * PLANE_BYTES)          // 40960
#define SMEM_TOTAL (2 * STAGE_BYTES)           // 81920

__global__ __launch_bounds__(256) void k_gemm_mma(
    const __nv_bfloat16* __restrict__ Ah, const __nv_bfloat16* __restrict__ Al,
    const __nv_bfloat16* __restrict__ Xh, const __nv_bfloat16* __restrict__ Xl,
    const __nv_bfloat16* __restrict__ Wh, const __nv_bfloat16* __restrict__ Wl,
    const float* __restrict__ bias, float* __restrict__ out,
    __nv_bfloat16* __restrict__ Hh, __nv_bfloat16* __restrict__ Hl,
    int n, int outc, int do_relu)
{
    extern __shared__ char smem[];
    const uint32_t sb0 = smem_u32(smem);

    const int tid  = threadIdx.x;
    const int wid  = tid >> 5;
    const int lane = tid & 31;
    const int g    = lane >> 2;
    const int t    = lane & 3;
    const int m0   = blockIdx.x * 128;
    const int n0   = blockIdx.y * 128;
    const int warpM = (wid & 3) * 32;
    const int warpN = (wid >> 2) * 64;

    // ldmatrix per-lane element offsets (sans kk / plane)
    // A (x4): lanes 0-15 -> rows 0-15 @ col 0; lanes 16-31 -> rows 0-15 @ col 8
    const int aOff = (warpM + (lane & 15)) * LDT + ((lane >> 4) << 3);
    // B (x4, pair p covers ni=2p,2p+1): lanes 0-7 rows(p) col0; 8-15 rows col8;
    // 16-23 rows+8 col0; 24-31 rows+8 col8
    int bOff[4];
#pragma unroll
    for (int p = 0; p < 4; ++p)
        bOff[p] = (warpN + p * 16 + (lane & 7) + ((lane & 16) ? 8 : 0)) * LDT
                + ((lane & 8) ? 8 : 0);

    // staging map: 2 threads per row, 32B each
    const int srow = tid >> 1;
    const int shalf = tid & 1;
    int anode = m0 + srow; if (anode >= n) anode = n - 1;
    const size_t aoffA = (size_t)anode * KA;
    const size_t aoffX = (size_t)anode * 256;
    const size_t boff  = (size_t)(n0 + srow) * KTOT;
    const uint32_t sdst = srow * (LDT * 2) + shalf * 32;

#define STAGE(KT, STG) do {                                                    \
        int kbase_ = (KT) * BK;                                                \
        uint32_t sb_ = sb0 + (STG) * STAGE_BYTES + sdst;                       \
        const char* pah_; const char* pal_;                                    \
        if (kbase_ < KA) {                                                     \
            pah_ = (const char*)(Ah + aoffA + kbase_) + shalf * 32;            \
            pal_ = (const char*)(Al + aoffA + kbase_) + shalf * 32;            \
        } else {                                                               \
            pah_ = (const char*)(Xh + aoffX + (kbase_ - KA)) + shalf * 32;     \
            pal_ = (const char*)(Xl + aoffX + (kbase_ - KA)) + shalf * 32;     \
        }                                                                      \
        const char* pbh_ = (const char*)(Wh + boff + kbase_) + shalf * 32;     \
        const char* pbl_ = (const char*)(Wl + boff + kbase_) + shalf * 32;     \
        cpa16(sb_ + OFF_AH,      pah_);      cpa16(sb_ + OFF_AH + 16, pah_ + 16); \
        cpa16(sb_ + OFF_AL,      pal_);      cpa16(sb_ + OFF_AL + 16, pal_ + 16); \
        cpa16(sb_ + OFF_BH,      pbh_);      cpa16(sb_ + OFF_BH + 16, pbh_ + 16); \
        cpa16(sb_ + OFF_BL,      pbl_);      cpa16(sb_ + OFF_BL + 16, pbl_ + 16); \
        asm volatile("cp.async.commit_group;");                                \
    } while (0)

    float acc[2][8][4];
#pragma unroll
    for (int mi = 0; mi < 2; ++mi)
#pragma unroll
        for (int ni = 0; ni < 8; ++ni)
#pragma unroll
            for (int c = 0; c < 4; ++c) acc[mi][ni][c] = 0.0f;

    const int KT = KTOT / BK;   // 72
    STAGE(0, 0);

    for (int kt = 0; kt < KT; ++kt) {
        int cur = kt & 1;
        if (kt + 1 < KT) {
            STAGE(kt + 1, cur ^ 1);
            asm volatile("cp.async.wait_group 1;");
        } else {
            asm volatile("cp.async.wait_group 0;");
        }
        __syncthreads();

        const uint32_t sAh = sb0 + cur * STAGE_BYTES + OFF_AH;
        const uint32_t sAl = sb0 + cur * STAGE_BYTES + OFF_AL;
        const uint32_t sBh = sb0 + cur * STAGE_BYTES + OFF_BH;
        const uint32_t sBl = sb0 + cur * STAGE_BYTES + OFF_BL;

#pragma unroll
        for (int ks = 0; ks < 2; ++ks) {
            const int kk = ks * 16;
            uint32_t ah[2][4], al[2][4];
#pragma unroll
            for (int mi = 0; mi < 2; ++mi) {
                uint32_t eo = (uint32_t)(aOff + mi * 16 * LDT + kk) * 2;
                LDSM4(ah[mi], sAh + eo);
                LDSM4(al[mi], sAl + eo);
            }
#pragma unroll
            for (int p = 0; p < 4; ++p) {
                uint32_t bh[4], bl[4];
                uint32_t eo = (uint32_t)(bOff[p] + kk) * 2;
                LDSM4(bh, sBh + eo);
                LDSM4(bl, sBl + eo);
#pragma unroll
                for (int mi = 0; mi < 2; ++mi) {
                    MMA_BF16(acc[mi][2 * p],     ah[mi][0], ah[mi][1], ah[mi][2], ah[mi][3], bh[0], bh[1]);
                    MMA_BF16(acc[mi][2 * p],     al[mi][0], al[mi][1], al[mi][2], al[mi][3], bh[0], bh[1]);
                    MMA_BF16(acc[mi][2 * p],     ah[mi][0], ah[mi][1], ah[mi][2], ah[mi][3], bl[0], bl[1]);
                    MMA_BF16(acc[mi][2 * p + 1], ah[mi][0], ah[mi][1], ah[mi][2], ah[mi][3], bh[2], bh[3]);
                    MMA_BF16(acc[mi][2 * p + 1], al[mi][0], al[mi][1], al[mi][2], al[mi][3], bh[2], bh[3]);
                    MMA_BF16(acc[mi][2 * p + 1], ah[mi][0], ah[mi][1], ah[mi][2], ah[mi][3], bl[2], bl[3]);
                }
            }
        }
        __syncthreads();
    }

    // --- epilogue ---
#pragma unroll
    for (int mi = 0; mi < 2; ++mi) {
        int r0 = m0 + warpM + mi * 16 + g;
#pragma unroll
        for (int ni = 0; ni < 8; ++ni) {
            int c = n0 + warpN + ni * 8 + 2 * t;
            float b0 = bias[c], b1 = bias[c + 1];
            float v0 = acc[mi][ni][0] + b0;
            float v1 = acc[mi][ni][1] + b1;
            float v2 = acc[mi][ni][2] + b0;
            float v3 = acc[mi][ni][3] + b1;
            if (do_relu) {
                v0 = fmaxf(v0, 0.f); v1 = fmaxf(v1, 0.f);
                v2 = fmaxf(v2, 0.f); v3 = fmaxf(v3, 0.f);
            }
            if (r0 < n) {
                *(float2*)(out + (size_t)r0 * outc + c) = make_float2(v0, v1);
                if (Hh) {
                    __nv_bfloat162 hh = __floats2bfloat162_rn(v0, v1);
                    __nv_bfloat162 ll = __floats2bfloat162_rn(v0 - __low2float(hh),
                                                              v1 - __high2float(hh));
                    *(unsigned*)(Hh + (size_t)r0 * 256 + c) = *(unsigned*)&hh;
                    *(unsigned*)(Hl + (size_t)r0 * 256 + c) = *(unsigned*)&ll;
                }
            }
            if (r0 + 8 < n) {
                *(float2*)(out + (size_t)(r0 + 8) * outc + c) = make_float2(v2, v3);
                if (Hh) {
                    __nv_bfloat162 hh = __floats2bfloat162_rn(v2, v3);
                    __nv_bfloat162 ll = __floats2bfloat162_rn(v2 - __low2float(hh),
                                                              v3 - __high2float(hh));
                    *(unsigned*)(Hh + (size_t)(r0 + 8) * 256 + c) = *(unsigned*)&hh;
                    *(unsigned*)(Hl + (size_t)(r0 + 8) * 256 + c) = *(unsigned*)&ll;
                }
            }
        }
    }
}

// ---------------------------------------------------------------------------
extern "C" void kernel_launch(void* const* d_in, const int* in_sizes, int n_in,
                              void* d_out, int out_size)
{
    const float* x     = (const float*)d_in[0];
    const float* W1    = (const float*)d_in[1];
    const float* root1 = (const float*)d_in[2];
    const float* b1    = (const float*)d_in[3];
    const float* W2    = (const float*)d_in[4];
    const float* root2 = (const float*)d_in[5];
    const float* b2    = (const float*)d_in[6];
    const void*  ei    = d_in[7];
    const void*  et    = d_in[8];

    int E = in_sizes[8];
    int n = in_sizes[0] / 256;
    int nseg = n * R_REL;
    int sblk = (nseg + 255) / 256;

    __nv_bfloat16 *Ah, *Al, *X1h, *X1l, *X2h, *X2l, *Wh1, *Wl1, *Wh2, *Wl2;
    float* h;
    cudaGetSymbolAddress((void**)&Ah,  g_Ah);
    cudaGetSymbolAddress((void**)&Al,  g_Al);
    cudaGetSymbolAddress((void**)&X1h, g_X1h);
    cudaGetSymbolAddress((void**)&X1l, g_X1l);
    cudaGetSymbolAddress((void**)&X2h, g_X2h);
    cudaGetSymbolAddress((void**)&X2l, g_X2l);
    cudaGetSymbolAddress((void**)&Wh1, g_Wh1);
    cudaGetSymbolAddress((void**)&Wl1, g_Wl1);
    cudaGetSymbolAddress((void**)&Wh2, g_Wh2);
    cudaGetSymbolAddress((void**)&Wl2, g_Wl2);
    cudaGetSymbolAddress((void**)&h,   g_h);

    cudaFuncSetAttribute(k_gemm_mma, cudaFuncAttributeMaxDynamicSharedMemorySize, SMEM_TOTAL);

    dim3 g1((n + 127) / 128, 2);
    dim3 g2((n + 127) / 128, 1);

    // CSR build (once; shared by both layers)
    k_detect_zero<<<sblk, 256>>>((const unsigned*)ei, 2 * E, nseg);
    k_count<<<(E + 255) / 256, 256>>>(ei, et, E);
    k_scan1<<<sblk, 256>>>(nseg);
    k_scan2<<<sblk, 256>>>(nseg);
    k_scatter<<<(E + 255) / 256, 256>>>(ei, et, E);

    // ---- layer 1 ----
    k_agg_csr<<<(nseg + 7) / 8, 256>>>(x, Ah, Al, nseg);
    k_wconv<<<(384 * KTOT + 255) / 256, 256>>>(W1, root1, W2, root2);
    k_xconv<<<(n * 256 + 255) / 256, 256>>>(x, n * 256);
    k_gemm_mma<<<g1, 256, SMEM_TOTAL>>>(Ah, Al, X1h, X1l, Wh1, Wl1, b1, h, X2h, X2l, n, 256, 1);

    // ---- layer 2 ----
    k_agg_csr<<<(nseg + 7) / 8, 256>>>(h, Ah, Al, nseg);
    k_gemm_mma<<<g2, 256, SMEM_TOTAL>>>(Ah, Al, X2h, X2l, Wh2, Wl2, b2, (float*)d_out,
                                        (__nv_bfloat16*)nullptr, (__nv_bfloat16*)nullptr,
                                        n, 128, 0);
}

// round 8
// speedup vs baseline: 1.0538x; 1.0538x over previous
#include <cuda_runtime.h>
#include <cuda_bf16.h>
#include <cstdint>

#define N_NODES 20000
#define R_REL   8
#define KA      2048
#define KTOT    2304
#define BK      32
#define LDTS    36              // fp32 SMEM stride (32 + 4 pad)
#define NSEG_MX (N_NODES * R_REL)
#define E_MAX   650000

// ---------------- static device scratch ----------------
__device__ float g_A[(size_t)N_NODES * KA];     // tf32-rounded aggregated feats
__device__ float g_xt[(size_t)N_NODES * 256];   // tf32-rounded x
__device__ float g_h[(size_t)N_NODES * 256];    // layer-1 activations (fp32)
__device__ float g_ht[(size_t)N_NODES * 256];   // tf32-rounded h
__device__ float g_Wt1[256 * KTOT];             // [outc][K] tf32-rounded
__device__ float g_Wt2[128 * KTOT];
__device__ int   g_cnt[NSEG_MX];
__device__ int   g_off[NSEG_MX + 1];
__device__ int   g_cur[NSEG_MX];
__device__ int   g_part[(NSEG_MX + 255) / 256];
__device__ int   g_sorted[E_MAX];
__device__ int   g_is64;

__device__ __forceinline__ int load_idx(const void* p, long long i, int is64) {
    return is64 ? (int)((const long long*)p)[i] : ((const int*)p)[i];
}
__device__ __forceinline__ float tf32r(float v) {
    uint32_t r;
    asm("cvt.rna.tf32.f32 %0, %1;" : "=r"(r) : "f"(v));
    return __uint_as_float(r);
}

// ---------------- prep kernels ----------------
__global__ void k_detect_zero(const unsigned* __restrict__ ei_words, int nwords, int nseg) {
    int i = blockIdx.x * blockDim.x + threadIdx.x;
    if (i == 0) {
        int is64 = 1;
        int lim = nwords < 256 ? nwords : 256;
        for (int j = 1; j < lim; j += 2)
            if (ei_words[j] != 0u) { is64 = 0; break; }
        g_is64 = is64;
    }
    if (i < nseg) g_cnt[i] = 0;
}

__global__ void k_count(const void* __restrict__ ei, const void* __restrict__ et, int E) {
    int e = blockIdx.x * blockDim.x + threadIdx.x;
    if (e >= E) return;
    int is64 = g_is64;
    int dst = load_idx(ei, (long long)E + e, is64);
    int r   = load_idx(et, e, is64);
    atomicAdd(&g_cnt[dst * R_REL + r], 1);
}

__global__ void k_scan1(int nseg) {
    __shared__ int sh[256];
    int b = blockIdx.x, t = threadIdx.x, i = b * 256 + t;
    int v = (i < nseg) ? g_cnt[i] : 0;
    sh[t] = v; __syncthreads();
#pragma unroll
    for (int d = 1; d < 256; d <<= 1) {
        int add = (t >= d) ? sh[t - d] : 0;
        __syncthreads();
        sh[t] += add;
        __syncthreads();
    }
    if (i < nseg) g_off[i + 1] = sh[t];
    if (t == 255) g_part[b] = sh[255];
}

__global__ void k_scan2(int nseg) {
    __shared__ int sh[256];
    int b = blockIdx.x, t = threadIdx.x, i = b * 256 + t;
    int s = 0;
    for (int j = t; j < b; j += 256) s += g_part[j];
    sh[t] = s; __syncthreads();
#pragma unroll
    for (int d = 128; d > 0; d >>= 1) { if (t < d) sh[t] += sh[t + d]; __syncthreads(); }
    int base = sh[0];
    int selfv = (i < nseg) ? g_off[i + 1] : 0;
    int prev  = (t > 0 && i < nseg) ? g_off[i] : 0;
    __syncthreads();
    if (i < nseg) {
        g_off[i + 1] = selfv + base;
        g_cur[i] = base + prev;
    }
    if (b == 0 && t == 0) g_off[0] = 0;
}

__global__ void k_scatter(const void* __restrict__ ei, const void* __restrict__ et, int E) {
    int e = blockIdx.x * blockDim.x + threadIdx.x;
    if (e >= E) return;
    int is64 = g_is64;
    int src = load_idx(ei, e, is64);
    int dst = load_idx(ei, (long long)E + e, is64);
    int r   = load_idx(et, e, is64);
    int pos = atomicAdd(&g_cur[dst * R_REL + r], 1);
    g_sorted[pos] = src;
}

// ---------------- CSR aggregation: warp per (dst,rel) segment ----------------
__global__ __launch_bounds__(256) void k_agg_csr(
    const float* __restrict__ x, float* __restrict__ A, int nseg)
{
    int w = (int)(((size_t)blockIdx.x * blockDim.x + threadIdx.x) >> 5);
    if (w >= nseg) return;
    int lane = threadIdx.x & 31;
    int beg = g_off[w], end = g_off[w + 1];
    int cnt = end - beg;

    float4 a0 = make_float4(0.f, 0.f, 0.f, 0.f);
    float4 a1 = make_float4(0.f, 0.f, 0.f, 0.f);

    for (int base = beg; base < end; base += 32) {
        int m = end - base; if (m > 32) m = 32;
        int myE = (lane < m) ? g_sorted[base + lane] : 0;
        for (int j = 0; j < m; ++j) {
            int src = __shfl_sync(0xffffffffu, myE, j);
            const float4* xs = (const float4*)(x + (size_t)src * 256 + lane * 8);
            float4 v0 = xs[0], v1 = xs[1];
            a0.x += v0.x; a0.y += v0.y; a0.z += v0.z; a0.w += v0.w;
            a1.x += v1.x; a1.y += v1.y; a1.z += v1.z; a1.w += v1.w;
        }
    }
    float s = cnt > 0 ? 1.0f / (float)cnt : 0.0f;
    float4 o0, o1;
    o0.x = tf32r(a0.x * s); o0.y = tf32r(a0.y * s);
    o0.z = tf32r(a0.z * s); o0.w = tf32r(a0.w * s);
    o1.x = tf32r(a1.x * s); o1.y = tf32r(a1.y * s);
    o1.z = tf32r(a1.z * s); o1.w = tf32r(a1.w * s);

    float* dst = A + (size_t)w * 256 + lane * 8;
    *(float4*)(dst)     = o0;
    *(float4*)(dst + 4) = o1;
}

// ---------------- weight / input conversion (tf32 rounding) ----------------
__global__ void k_wconv(const float* __restrict__ W1, const float* __restrict__ r1,
                        const float* __restrict__ W2, const float* __restrict__ r2) {
    int idx = blockIdx.x * blockDim.x + threadIdx.x;
    const int L1 = 256 * KTOT, L2 = 128 * KTOT;
    if (idx < L1) {
        int nrow = idx / KTOT, k = idx % KTOT;
        float v = (k < KA) ? W1[(size_t)k * 256 + nrow] : r1[(size_t)(k - KA) * 256 + nrow];
        g_Wt1[idx] = tf32r(v);
    } else if (idx < L1 + L2) {
        int i2 = idx - L1;
        int nrow = i2 / KTOT, k = i2 % KTOT;
        float v = (k < KA) ? W2[(size_t)k * 128 + nrow] : r2[(size_t)(k - KA) * 128 + nrow];
        g_Wt2[i2] = tf32r(v);
    }
}

__global__ void k_xconv(const float* __restrict__ x, int total) {
    int idx = blockIdx.x * blockDim.x + threadIdx.x;
    if (idx >= total) return;
    g_xt[idx] = tf32r(x[idx]);
}

// ---------------- pipelined tf32 mma.sync GEMM ----------------
#define MMA_TF32(C, A0, A1, A2, A3, B0, B1)                                   \
    asm volatile(                                                             \
        "mma.sync.aligned.m16n8k8.row.col.f32.tf32.tf32.f32 "                 \
        "{%0,%1,%2,%3}, {%4,%5,%6,%7}, {%8,%9}, {%0,%1,%2,%3};"               \
        : "+f"(C[0]), "+f"(C[1]), "+f"(C[2]), "+f"(C[3])                      \
        : "r"(A0), "r"(A1), "r"(A2), "r"(A3), "r"(B0), "r"(B1))

__device__ __forceinline__ uint32_t smem_u32(const void* p) {
    uint32_t a;
    asm("{ .reg .u64 t; cvta.to.shared.u64 t, %1; cvt.u32.u64 %0, t; }" : "=r"(a) : "l"(p));
    return a;
}
__device__ __forceinline__ void cpa16(uint32_t dst, const void* src) {
    asm volatile("cp.async.cg.shared.global [%0], [%1], 16;" :: "r"(dst), "l"(src));
}

#define PLANE_BYTES (128 * LDTS * 4)           // 18432
#define OFF_A 0
#define OFF_B (PLANE_BYTES)
#define STAGE_BYTES (2 * PLANE_BYTES)          // 36864
#define SMEM_TOTAL (2 * STAGE_BYTES)           // 73728

__global__ __launch_bounds__(256) void k_gemm_tf32(
    const float* __restrict__ Aagg, const float* __restrict__ Xt,
    const float* __restrict__ Wt,
    const float* __restrict__ bias, float* __restrict__ out,
    float* __restrict__ H, float* __restrict__ Ht,   // layer-1 extras (or null)
    int n, int outc, int do_relu)
{
    extern __shared__ char smem[];
    const uint32_t sb0 = smem_u32(smem);

    const int tid  = threadIdx.x;
    const int wid  = tid >> 5;
    const int lane = tid & 31;
    const int g    = lane >> 2;
    const int t    = lane & 3;
    const int m0   = blockIdx.x * 128;
    const int n0   = blockIdx.y * 128;
    const int warpM = (wid & 3) * 32;
    const int warpN = (wid >> 2) * 64;

    // staging map: 2 threads per row, 64B each (row = 32 floats = 128B)
    const int srow  = tid >> 1;
    const int shalf = tid & 1;
    int anode = m0 + srow; if (anode >= n) anode = n - 1;
    const size_t aoffA = (size_t)anode * KA;
    const size_t aoffX = (size_t)anode * 256;
    const size_t boff  = (size_t)(n0 + srow) * KTOT;
    const uint32_t sdst = srow * (LDTS * 4) + shalf * 64;

#define STAGE(KT, STG) do {                                                    \
        int kbase_ = (KT) * BK;                                                \
        uint32_t sb_ = sb0 + (STG) * STAGE_BYTES + sdst;                       \
        const char* pa_;                                                       \
        if (kbase_ < KA)                                                       \
            pa_ = (const char*)(Aagg + aoffA + kbase_) + shalf * 64;           \
        else                                                                   \
            pa_ = (const char*)(Xt + aoffX + (kbase_ - KA)) + shalf * 64;      \
        const char* pb_ = (const char*)(Wt + boff + kbase_) + shalf * 64;      \
        cpa16(sb_ + OFF_A,      pa_);      cpa16(sb_ + OFF_A + 16, pa_ + 16);  \
        cpa16(sb_ + OFF_A + 32, pa_ + 32); cpa16(sb_ + OFF_A + 48, pa_ + 48);  \
        cpa16(sb_ + OFF_B,      pb_);      cpa16(sb_ + OFF_B + 16, pb_ + 16);  \
        cpa16(sb_ + OFF_B + 32, pb_ + 32); cpa16(sb_ + OFF_B + 48, pb_ + 48);  \
        asm volatile("cp.async.commit_group;");                                \
    } while (0)

    float acc[2][8][4];
#pragma unroll
    for (int mi = 0; mi < 2; ++mi)
#pragma unroll
        for (int ni = 0; ni < 8; ++ni)
#pragma unroll
            for (int c = 0; c < 4; ++c) acc[mi][ni][c] = 0.0f;

    const int KT = KTOT / BK;   // 72
    STAGE(0, 0);

    for (int kt = 0; kt < KT; ++kt) {
        int cur = kt & 1;
        if (kt + 1 < KT) {
            STAGE(kt + 1, cur ^ 1);
            asm volatile("cp.async.wait_group 1;");
        } else {
            asm volatile("cp.async.wait_group 0;");
        }
        __syncthreads();

        const float* sA = (const float*)(smem + cur * STAGE_BYTES + OFF_A);
        const float* sB = (const float*)(smem + cur * STAGE_BYTES + OFF_B);

#pragma unroll
        for (int ks = 0; ks < 4; ++ks) {
            const int kk = ks * 8;
            uint32_t a[2][4];
#pragma unroll
            for (int mi = 0; mi < 2; ++mi) {
                int base0 = (warpM + mi * 16 + g) * LDTS + kk + t;
                int base1 = base0 + 8 * LDTS;
                a[mi][0] = *(const uint32_t*)&sA[base0];
                a[mi][1] = *(const uint32_t*)&sA[base1];
                a[mi][2] = *(const uint32_t*)&sA[base0 + 4];
                a[mi][3] = *(const uint32_t*)&sA[base1 + 4];
            }
#pragma unroll
            for (int ni = 0; ni < 8; ++ni) {
                int o = (warpN + ni * 8 + g) * LDTS + kk + t;
                uint32_t b0 = *(const uint32_t*)&sB[o];
                uint32_t b1 = *(const uint32_t*)&sB[o + 4];
#pragma unroll
                for (int mi = 0; mi < 2; ++mi)
                    MMA_TF32(acc[mi][ni], a[mi][0], a[mi][1], a[mi][2], a[mi][3], b0, b1);
            }
        }
        __syncthreads();
    }

    // --- epilogue ---
#pragma unroll
    for (int mi = 0; mi < 2; ++mi) {
        int r0 = m0 + warpM + mi * 16 + g;
#pragma unroll
        for (int ni = 0; ni < 8; ++ni) {
            int c = n0 + warpN + ni * 8 + 2 * t;
            float b0 = bias[c], b1 = bias[c + 1];
            float v0 = acc[mi][ni][0] + b0;
            float v1 = acc[mi][ni][1] + b1;
            float v2 = acc[mi][ni][2] + b0;
            float v3 = acc[mi][ni][3] + b1;
            if (do_relu) {
                v0 = fmaxf(v0, 0.f); v1 = fmaxf(v1, 0.f);
                v2 = fmaxf(v2, 0.f); v3 = fmaxf(v3, 0.f);
            }
            if (r0 < n) {
                *(float2*)(out + (size_t)r0 * outc + c) = make_float2(v0, v1);
                if (H) {
                    *(float2*)(H + (size_t)r0 * 256 + c) = make_float2(v0, v1);
                    *(float2*)(Ht + (size_t)r0 * 256 + c) =
                        make_float2(tf32r(v0), tf32r(v1));
                }
            }
            if (r0 + 8 < n) {
                *(float2*)(out + (size_t)(r0 + 8) * outc + c) = make_float2(v2, v3);
                if (H) {
                    *(float2*)(H + (size_t)(r0 + 8) * 256 + c) = make_float2(v2, v3);
                    *(float2*)(Ht + (size_t)(r0 + 8) * 256 + c) =
                        make_float2(tf32r(v2), tf32r(v3));
                }
            }
        }
    }
}

// ---------------------------------------------------------------------------
extern "C" void kernel_launch(void* const* d_in, const int* in_sizes, int n_in,
                              void* d_out, int out_size)
{
    const float* x     = (const float*)d_in[0];
    const float* W1    = (const float*)d_in[1];
    const float* root1 = (const float*)d_in[2];
    const float* b1    = (const float*)d_in[3];
    const float* W2    = (const float*)d_in[4];
    const float* root2 = (const float*)d_in[5];
    const float* b2    = (const float*)d_in[6];
    const void*  ei    = d_in[7];
    const void*  et    = d_in[8];

    int E = in_sizes[8];
    int n = in_sizes[0] / 256;
    int nseg = n * R_REL;
    int sblk = (nseg + 255) / 256;

    float *A, *xt, *h, *ht, *Wt1, *Wt2;
    cudaGetSymbolAddress((void**)&A,   g_A);
    cudaGetSymbolAddress((void**)&xt,  g_xt);
    cudaGetSymbolAddress((void**)&h,   g_h);
    cudaGetSymbolAddress((void**)&ht,  g_ht);
    cudaGetSymbolAddress((void**)&Wt1, g_Wt1);
    cudaGetSymbolAddress((void**)&Wt2, g_Wt2);

    cudaFuncSetAttribute(k_gemm_tf32, cudaFuncAttributeMaxDynamicSharedMemorySize, SMEM_TOTAL);

    dim3 g1((n + 127) / 128, 2);
    dim3 g2((n + 127) / 128, 1);

    // CSR build (once; shared by both layers)
    k_detect_zero<<<sblk, 256>>>((const unsigned*)ei, 2 * E, nseg);
    k_count<<<(E + 255) / 256, 256>>>(ei, et, E);
    k_scan1<<<sblk, 256>>>(nseg);
    k_scan2<<<sblk, 256>>>(nseg);
    k_scatter<<<(E + 255) / 256, 256>>>(ei, et, E);

    // ---- layer 1 ----
    k_agg_csr<<<(nseg + 7) / 8, 256>>>(x, A, nseg);
    k_wconv<<<(384 * KTOT + 255) / 256, 256>>>(W1, root1, W2, root2);
    k_xconv<<<(n * 256 + 255) / 256, 256>>>(x, n * 256);
    k_gemm_tf32<<<g1, 256, SMEM_TOTAL>>>(A, xt, Wt1, b1, h, h, ht, n, 256, 1);

    // ---- layer 2 ----
    k_agg_csr<<<(nseg + 7) / 8, 256>>>(h, A, nseg);
    k_gemm_tf32<<<g2, 256, SMEM_TOTAL>>>(A, ht, Wt2, b2, (float*)d_out,
                                         (float*)nullptr, (float*)nullptr, n, 128, 0);
}